// round 1
// baseline (speedup 1.0000x reference)
#include <cuda_runtime.h>
#include <math.h>

#define NDIM 512
#define BATCH 256

// Scratch for the projected weight vectors u = B^T w_h, v = B^T w_v.
__device__ float g_u[NDIM];
__device__ float g_v[NDIM];

// ---------------------------------------------------------------------------
// Kernel A: block k computes u[k] and v[k].
//   basis[i,k] = cu[i] * cos((2k+1) * i * pi / 1024)
//   u[k] = sum_i basis[i,k] * w_h[i],   v[k] = sum_i basis[i,k] * w_v[i]
// Integer-exact argument reduction: (2k+1)*i mod 2048, then * (pi/1024).
// ---------------------------------------------------------------------------
__global__ __launch_bounds__(256) void proj_kernel(const float* __restrict__ wh,
                                                   const float* __restrict__ wv) {
    const int k = blockIdx.x;
    const int t = threadIdx.x;
    const int twoK1 = 2 * k + 1;
    const float step = 3.14159265358979323846f / 1024.0f;

    float su = 0.0f, sv = 0.0f;
#pragma unroll
    for (int r = 0; r < 2; ++r) {
        const int i = t + r * 256;
        const int m = (twoK1 * i) & 2047;          // exact mod-2pi reduction
        const float c = cosf((float)m * step);     // arg in [0, 2pi)
        const float cu = (i == 0) ? 0.04419417382415922f   // sqrt(1/512)
                                  : 0.0625f;               // sqrt(2/512)
        const float bc = cu * c;
        su = fmaf(bc, wh[i], su);
        sv = fmaf(bc, wv[i], sv);
    }

    // warp reduction (8 warps)
#pragma unroll
    for (int o = 16; o; o >>= 1) {
        su += __shfl_down_sync(0xffffffffu, su, o);
        sv += __shfl_down_sync(0xffffffffu, sv, o);
    }
    __shared__ float s_u[8];
    __shared__ float s_v[8];
    if ((t & 31) == 0) { s_u[t >> 5] = su; s_v[t >> 5] = sv; }
    __syncthreads();
    if (t < 32) {
        float a = (t < 8) ? s_u[t] : 0.0f;
        float b = (t < 8) ? s_v[t] : 0.0f;
#pragma unroll
        for (int o = 4; o; o >>= 1) {
            a += __shfl_down_sync(0xffffffffu, a, o);
            b += __shfl_down_sync(0xffffffffu, b, o);
        }
        if (t == 0) { g_u[k] = a; g_v[k] = b; }
    }
}

// ---------------------------------------------------------------------------
// Kernel B: one block per batch row. out[b] = sigmoid(u^T X_b v + bias).
// Thread t handles float4 elements at flat-index 4t + 2048*i:
//   column slice l = (4t) & 511 is LOOP-INVARIANT -> v4 loaded once;
//   row index k = k0 + 4i -> one broadcast shared load per iteration.
// Streams 1 MB/block via __ldcs (no reuse -> bypass L2 persistence).
// Double accumulator: fp64 adds fully hidden under HBM latency.
// ---------------------------------------------------------------------------
__global__ __launch_bounds__(512) void dot_kernel(const float* __restrict__ x,
                                                  const float* __restrict__ bias,
                                                  float* __restrict__ out) {
    __shared__ __align__(16) float su[NDIM];
    __shared__ __align__(16) float sv[NDIM];
    const int t = threadIdx.x;
    const int b = blockIdx.x;

    su[t] = g_u[t];
    sv[t] = g_v[t];
    __syncthreads();

    const float4* __restrict__ xr =
        reinterpret_cast<const float4*>(x + (size_t)b * NDIM * NDIM);

    const int l  = (4 * t) & 511;   // 16B aligned (multiple of 4 floats)
    const int k0 = (4 * t) >> 9;    // 0..3
    const float4 v4 = *reinterpret_cast<const float4*>(&sv[l]);

    double acc = 0.0;
#pragma unroll 4
    for (int i = 0; i < 128; ++i) {
        const float4 xx = __ldcs(&xr[t + 512 * i]);
        const float uk = su[k0 + 4 * i];
        float d = xx.x * v4.x;
        d = fmaf(xx.y, v4.y, d);
        d = fmaf(xx.z, v4.z, d);
        d = fmaf(xx.w, v4.w, d);
        acc += (double)(uk * d);
    }

    // reduce 512 threads (16 warps)
#pragma unroll
    for (int o = 16; o; o >>= 1)
        acc += __shfl_down_sync(0xffffffffu, acc, o);

    __shared__ double wsum[16];
    if ((t & 31) == 0) wsum[t >> 5] = acc;
    __syncthreads();
    if (t < 32) {
        double s = (t < 16) ? wsum[t] : 0.0;
#pragma unroll
        for (int o = 8; o; o >>= 1)
            s += __shfl_down_sync(0xffffffffu, s, o);
        if (t == 0) {
            const float val = (float)s + bias[0];
            out[b] = 1.0f / (1.0f + expf(-val));
        }
    }
}

extern "C" void kernel_launch(void* const* d_in, const int* in_sizes, int n_in,
                              void* d_out, int out_size) {
    const float* x    = (const float*)d_in[0];
    const float* wh   = (const float*)d_in[1];
    const float* wv   = (const float*)d_in[2];
    const float* bias = (const float*)d_in[3];
    float* out = (float*)d_out;

    proj_kernel<<<NDIM, 256>>>(wh, wv);
    dot_kernel<<<BATCH, 512>>>(x, bias, out);
}